// round 4
// baseline (speedup 1.0000x reference)
#include <cuda_runtime.h>
#include <cstdint>

// Problem constants (fixed by setup_inputs)
#define BB 4
#define CC 128
#define HH 96
#define WW 160
#define RR 4
#define SS 17   // 1 + 4*R

// Tiling
#define TW 32
#define TH 8
#define BX 16          // threads in w (2 px each)
#define BY 8
#define NTHREADS (BX * BY)   // 128
#define HALO_W (TW + 2 * RR) // 40
#define HALO_H (TH + 2 * RR) // 16
#define HALO_N (HALO_H * HALO_W)  // 640

#define NCHUNK 16
#define CPK (CC / NCHUNK)    // 8 channels per chunk
#define HW (HH * WW)

// packed f32x2 fma: acc = a*b + acc  (elementwise on 2 floats)
__device__ __forceinline__ void ffma2(uint64_t& acc, uint64_t a, uint64_t b) {
    asm("fma.rn.f32x2 %0, %1, %2, %0;" : "+l"(acc) : "l"(a), "l"(b));
}
__device__ __forceinline__ uint64_t pack2(float lo, float hi) {
    uint64_t r;
    asm("mov.b64 %0, {%1, %2};" : "=l"(r) : "f"(lo), "f"(hi));
    return r;
}

__global__ __launch_bounds__(NTHREADS, 6)
void cost_volume_kernel(const float* __restrict__ src,
                        const float* __restrict__ tgt,
                        float* __restrict__ out) {
    __shared__ float sm[CPK * HALO_N];   // 8 * 640 * 4B = 20 KB

    const int tx = threadIdx.x;
    const int ty = threadIdx.y;
    const int tid = ty * BX + tx;
    const int w0 = blockIdx.x * TW;
    const int h0 = blockIdx.y * TH;
    const int b     = blockIdx.z >> 4;   // NCHUNK = 16
    const int chunk = blockIdx.z & 15;
    const int c0 = chunk * CPK;
    const int lx = 2 * tx;
    const int w  = w0 + lx;
    const int h  = h0 + ty;

    const float* tgtb = tgt + ((long long)b * CC + c0) * HW;
    const float* srcp = src + (((long long)b * CC + c0) * HH + h) * WW + w;

    // ---- prefetch all CPK src pixel pairs (independent LDG.64, MLP=8) ----
    uint64_t sv[CPK];
#pragma unroll
    for (int ch = 0; ch < CPK; ch++)
        sv[ch] = *(const uint64_t*)(srcp + ch * HW);

    // ---- staging: precompute 5 offsets/masks once, then unrolled LDG/STS ----
    int soff[5], goff[5];
    bool val[5];
#pragma unroll
    for (int k = 0; k < 5; k++) {
        int pos = tid + k * NTHREADS;     // 0..639
        int r   = pos / HALO_W;
        int cl  = pos - r * HALO_W;
        int gr  = h0 - RR + r;
        int gc  = w0 - RR + cl;
        soff[k] = pos;
        val[k]  = ((unsigned)gr < (unsigned)HH) & ((unsigned)gc < (unsigned)WW);
        goff[k] = gr * WW + gc;
    }
#pragma unroll
    for (int ch = 0; ch < CPK; ch++) {
        const float* tc = tgtb + ch * HW;
        float* sc = sm + ch * HALO_N;
#pragma unroll
        for (int k = 0; k < 5; k++)
            sc[soff[k]] = val[k] ? tc[goff[k]] : 0.f;
    }
    __syncthreads();

    // ---- compute: 17 packed accumulators over CPK channels (fully unrolled) ----
    uint64_t acc[SS];
#pragma unroll
    for (int s = 0; s < SS; s++) acc[s] = 0ull;

    const int rowbase = (ty + RR) * HALO_W + lx;     // this thread's row, col lx

#pragma unroll
    for (int ch = 0; ch < CPK; ch++) {
        const float* smc = sm + ch * HALO_N;
        // horizontal row: 10 values v[0..9] = cols lx..lx+9 (5 aligned LDS.64)
        float2 t0 = *(const float2*)(smc + rowbase + 0);
        float2 t1 = *(const float2*)(smc + rowbase + 2);
        float2 t2 = *(const float2*)(smc + rowbase + 4);
        float2 t3 = *(const float2*)(smc + rowbase + 6);
        float2 t4 = *(const float2*)(smc + rowbase + 8);

        // s=0: center pair (v4,v5)
        ffma2(acc[0], sv[ch], pack2(t2.x, t2.y));
        // i=1: L=(v3,v4) R=(v5,v6)
        ffma2(acc[3], sv[ch], pack2(t1.y, t2.x));
        ffma2(acc[4], sv[ch], pack2(t2.y, t3.x));
        // i=2: L=(v2,v3)  R=(v6,v7)
        ffma2(acc[7], sv[ch], pack2(t1.x, t1.y));
        ffma2(acc[8], sv[ch], pack2(t3.x, t3.y));
        // i=3: L=(v1,v2) R=(v7,v8)
        ffma2(acc[11], sv[ch], pack2(t0.y, t1.x));
        ffma2(acc[12], sv[ch], pack2(t3.y, t4.x));
        // i=4: L=(v0,v1)  R=(v8,v9)
        ffma2(acc[15], sv[ch], pack2(t0.x, t0.y));
        ffma2(acc[16], sv[ch], pack2(t4.x, t4.y));

        // vertical: s=4i-3 (up), s=4i-2 (down): aligned pairs at col lx+RR
#pragma unroll
        for (int i2 = 1; i2 <= RR; i2++) {
            uint64_t tu = *(const uint64_t*)(smc + (ty + RR - i2) * HALO_W + lx + RR);
            uint64_t td = *(const uint64_t*)(smc + (ty + RR + i2) * HALO_W + lx + RR);
            ffma2(acc[4 * i2 - 3], sv[ch], tu);
            ffma2(acc[4 * i2 - 2], sv[ch], td);
        }
    }

    // ---- combine partials across chunks via float2 atomics ----
    float* ob = out + ((((long long)b * SS) * HH) + h) * WW + w;
#pragma unroll
    for (int s = 0; s < SS; s++) {
        float2 o;
        asm("mov.b64 {%0, %1}, %2;" : "=f"(o.x), "=f"(o.y) : "l"(acc[s]));
        atomicAdd((float2*)(ob + s * HW), o);
    }
}

extern "C" void kernel_launch(void* const* d_in, const int* in_sizes, int n_in,
                              void* d_out, int out_size) {
    const float* src = (const float*)d_in[0];
    const float* tgt = (const float*)d_in[1];
    float* out = (float*)d_out;

    cudaMemsetAsync(out, 0, (size_t)out_size * sizeof(float), 0);

    dim3 block(BX, BY);
    dim3 grid(WW / TW, HH / TH, BB * NCHUNK);   // 5 x 12 x 64 = 3840 CTAs
    cost_volume_kernel<<<grid, block>>>(src, tgt, out);
}

// round 5
// speedup vs baseline: 1.0072x; 1.0072x over previous
#include <cuda_runtime.h>
#include <cstdint>

// Problem constants (fixed by setup_inputs)
#define BB 4
#define CC 128
#define HH 96
#define WW 160
#define RR 4
#define SS 17   // 1 + 4*R

// Tiling: 32 (w) x 16 (h) tile, each thread owns 2x2 pixels
#define TW 32
#define TH 16
#define BX 16          // threads in w (2 px each)
#define BY 8           // threads in h (2 rows each)
#define NTHREADS (BX * BY)        // 128
#define HALO_W (TW + 2 * RR)      // 40
#define HALO_H (TH + 2 * RR)      // 24
#define HALO_N (HALO_H * HALO_W)  // 960

#define NCHUNK 16
#define CPK (CC / NCHUNK)    // 8 channels per chunk
#define HW (HH * WW)

// packed f32x2 fma: acc = a*b + acc  (elementwise on 2 floats)
__device__ __forceinline__ void ffma2(uint64_t& acc, uint64_t a, uint64_t b) {
    asm("fma.rn.f32x2 %0, %1, %2, %0;" : "+l"(acc) : "l"(a), "l"(b));
}
__device__ __forceinline__ uint64_t pack2(float lo, float hi) {
    uint64_t r;
    asm("mov.b64 %0, {%1, %2};" : "=l"(r) : "f"(lo), "f"(hi));
    return r;
}

__global__ __launch_bounds__(NTHREADS, 4)
void cost_volume_kernel(const float* __restrict__ src,
                        const float* __restrict__ tgt,
                        float* __restrict__ out) {
    __shared__ float sm[CPK * HALO_N];   // 8 * 960 * 4B = 30 KB

    const int tx = threadIdx.x;
    const int ty = threadIdx.y;
    const int tid = ty * BX + tx;
    const int w0 = blockIdx.x * TW;
    const int h0 = blockIdx.y * TH;
    const int b     = blockIdx.z >> 4;   // NCHUNK = 16
    const int chunk = blockIdx.z & 15;
    const int c0 = chunk * CPK;
    const int lx = 2 * tx;
    const int w  = w0 + lx;
    const int r0 = h0 + 2 * ty;          // this thread's first global row

    const float* tgtb  = tgt + ((long long)b * CC + c0) * HW;
    const float* srcp0 = src + (((long long)b * CC + c0) * HH + r0) * WW + w;

    // ---- staging offsets: 960 elems / 128 threads = 7.5 -> 8 slots ----
    int goff[8];
    bool val[8];
#pragma unroll
    for (int k = 0; k < 8; k++) {
        int pos = tid + k * NTHREADS;    // 0..1023
        int r   = pos / HALO_W;
        int cl  = pos - r * HALO_W;
        int gr  = h0 - RR + r;
        int gc  = w0 - RR + cl;
        val[k]  = (pos < HALO_N) & ((unsigned)gr < (unsigned)HH) & ((unsigned)gc < (unsigned)WW);
        goff[k] = gr * WW + gc;
    }
#pragma unroll
    for (int ch = 0; ch < CPK; ch++) {
        const float* tc = tgtb + ch * HW;
        float* sc = sm + ch * HALO_N;
#pragma unroll
        for (int k = 0; k < 8; k++) {
            int pos = tid + k * NTHREADS;
            bool ok = (k < 7) | (pos < HALO_N);
            if (ok) sc[pos] = val[k] ? tc[goff[k]] : 0.f;
        }
    }
    __syncthreads();

    // ---- compute: 17 shifts x 2 rows, packed over the 2-px pair ----
    uint64_t acc0[SS], acc1[SS];
#pragma unroll
    for (int s = 0; s < SS; s++) { acc0[s] = 0ull; acc1[s] = 0ull; }

    const int hr = 2 * ty + RR;          // halo row index of r0
    const int hbase = hr * HALO_W + lx;  // start of horizontal span, row r0
    const int vbase = lx + RR;           // center column in halo

#pragma unroll
    for (int ch = 0; ch < CPK; ch++) {
        const uint64_t sv0 = *(const uint64_t*)(srcp0 + ch * HW);
        const uint64_t sv1 = *(const uint64_t*)(srcp0 + ch * HW + WW);

        const float* smc = sm + ch * HALO_N;

        // horizontal spans (10 floats each) for rows r0 and r1
        float2 a0 = *(const float2*)(smc + hbase + 0);
        float2 a1 = *(const float2*)(smc + hbase + 2);
        float2 a2 = *(const float2*)(smc + hbase + 4);   // center pair row r0
        float2 a3 = *(const float2*)(smc + hbase + 6);
        float2 a4 = *(const float2*)(smc + hbase + 8);
        float2 b0 = *(const float2*)(smc + hbase + HALO_W + 0);
        float2 b1 = *(const float2*)(smc + hbase + HALO_W + 2);
        float2 b2 = *(const float2*)(smc + hbase + HALO_W + 4); // center pair row r1
        float2 b3 = *(const float2*)(smc + hbase + HALO_W + 6);
        float2 b4 = *(const float2*)(smc + hbase + HALO_W + 8);

        // vertical neighbor pairs (shared by both rows)
        const float* vc = smc + vbase;
        uint64_t vm4 = *(const uint64_t*)(vc + (hr - 4) * HALO_W);
        uint64_t vm3 = *(const uint64_t*)(vc + (hr - 3) * HALO_W);
        uint64_t vm2 = *(const uint64_t*)(vc + (hr - 2) * HALO_W);
        uint64_t vm1 = *(const uint64_t*)(vc + (hr - 1) * HALO_W);
        uint64_t vp2 = *(const uint64_t*)(vc + (hr + 2) * HALO_W);
        uint64_t vp3 = *(const uint64_t*)(vc + (hr + 3) * HALO_W);
        uint64_t vp4 = *(const uint64_t*)(vc + (hr + 4) * HALO_W);
        uint64_t vp5 = *(const uint64_t*)(vc + (hr + 5) * HALO_W);

        uint64_t ca = pack2(a2.x, a2.y);   // center pair row r0
        uint64_t cb = pack2(b2.x, b2.y);   // center pair row r1

        // ---- row r0 ----
        ffma2(acc0[0],  sv0, ca);
        ffma2(acc0[3],  sv0, pack2(a1.y, a2.x));
        ffma2(acc0[4],  sv0, pack2(a2.y, a3.x));
        ffma2(acc0[7],  sv0, pack2(a1.x, a1.y));
        ffma2(acc0[8],  sv0, pack2(a3.x, a3.y));
        ffma2(acc0[11], sv0, pack2(a0.y, a1.x));
        ffma2(acc0[12], sv0, pack2(a3.y, a4.x));
        ffma2(acc0[15], sv0, pack2(a0.x, a0.y));
        ffma2(acc0[16], sv0, pack2(a4.x, a4.y));
        // vertical: s=4i-3 row r0-i, s=4i-2 row r0+i
        ffma2(acc0[1],  sv0, vm1);
        ffma2(acc0[2],  sv0, cb);    // r0+1 == r1 center
        ffma2(acc0[5],  sv0, vm2);
        ffma2(acc0[6],  sv0, vp2);
        ffma2(acc0[9],  sv0, vm3);
        ffma2(acc0[10], sv0, vp3);
        ffma2(acc0[13], sv0, vm4);
        ffma2(acc0[14], sv0, vp4);

        // ---- row r1 ----
        ffma2(acc1[0],  sv1, cb);
        ffma2(acc1[3],  sv1, pack2(b1.y, b2.x));
        ffma2(acc1[4],  sv1, pack2(b2.y, b3.x));
        ffma2(acc1[7],  sv1, pack2(b1.x, b1.y));
        ffma2(acc1[8],  sv1, pack2(b3.x, b3.y));
        ffma2(acc1[11], sv1, pack2(b0.y, b1.x));
        ffma2(acc1[12], sv1, pack2(b3.y, b4.x));
        ffma2(acc1[15], sv1, pack2(b0.x, b0.y));
        ffma2(acc1[16], sv1, pack2(b4.x, b4.y));
        // vertical for r1: up i -> r1-i, down i -> r1+i
        ffma2(acc1[1],  sv1, ca);    // r1-1 == r0 center
        ffma2(acc1[2],  sv1, vp2);
        ffma2(acc1[5],  sv1, vm1);
        ffma2(acc1[6],  sv1, vp3);
        ffma2(acc1[9],  sv1, vm2);
        ffma2(acc1[10], sv1, vp4);
        ffma2(acc1[13], sv1, vm3);
        ffma2(acc1[14], sv1, vp5);
    }

    // ---- combine partials across chunks via float2 atomics ----
    float* ob = out + (((long long)b * SS) * HH + r0) * WW + w;
#pragma unroll
    for (int s = 0; s < SS; s++) {
        float2 o0, o1;
        asm("mov.b64 {%0, %1}, %2;" : "=f"(o0.x), "=f"(o0.y) : "l"(acc0[s]));
        asm("mov.b64 {%0, %1}, %2;" : "=f"(o1.x), "=f"(o1.y) : "l"(acc1[s]));
        atomicAdd((float2*)(ob + s * HW), o0);
        atomicAdd((float2*)(ob + s * HW + WW), o1);
    }
}

extern "C" void kernel_launch(void* const* d_in, const int* in_sizes, int n_in,
                              void* d_out, int out_size) {
    const float* src = (const float*)d_in[0];
    const float* tgt = (const float*)d_in[1];
    float* out = (float*)d_out;

    cudaMemsetAsync(out, 0, (size_t)out_size * sizeof(float), 0);

    dim3 block(BX, BY);                         // 16 x 8 = 128 threads
    dim3 grid(WW / TW, HH / TH, BB * NCHUNK);   // 5 x 6 x 64 = 1920 CTAs
    cost_volume_kernel<<<grid, block>>>(src, tgt, out);
}

// round 6
// speedup vs baseline: 1.0082x; 1.0010x over previous
#include <cuda_runtime.h>
#include <cstdint>

// Problem constants (fixed by setup_inputs)
#define BB 4
#define CC 128
#define HH 96
#define WW 160
#define RR 4
#define SS 17   // 1 + 4*R

// Tiling
#define TW 32
#define TH 8
#define BX 16          // threads in w (2 px each)
#define BY 8
#define NTHREADS (BX * BY)   // 128
#define HALO_W (TW + 2 * RR) // 40
#define HALO_H (TH + 2 * RR) // 16
#define HALO_N (HALO_H * HALO_W)  // 640

#define NCHUNK 16
#define CPK (CC / NCHUNK)    // 8 channels per chunk
#define HW (HH * WW)

// packed f32x2 fma: acc = a*b + acc  (elementwise on 2 floats)
__device__ __forceinline__ void ffma2(uint64_t& acc, uint64_t a, uint64_t b) {
    asm("fma.rn.f32x2 %0, %1, %2, %0;" : "+l"(acc) : "l"(a), "l"(b));
}
__device__ __forceinline__ uint64_t pack2(float lo, float hi) {
    uint64_t r;
    asm("mov.b64 %0, {%1, %2};" : "=l"(r) : "f"(lo), "f"(hi));
    return r;
}

__global__ __launch_bounds__(NTHREADS, 8)
void cost_volume_kernel(const float* __restrict__ src,
                        const float* __restrict__ tgt,
                        float* __restrict__ out) {
    __shared__ float sm[CPK * HALO_N];   // 8 * 640 * 4B = 20 KB

    const int tx = threadIdx.x;
    const int ty = threadIdx.y;
    const int tid = ty * BX + tx;
    const int w0 = blockIdx.x * TW;
    const int h0 = blockIdx.y * TH;
    const int b     = blockIdx.z >> 4;   // NCHUNK = 16
    const int chunk = blockIdx.z & 15;
    const int c0 = chunk * CPK;
    const int lx = 2 * tx;
    const int w  = w0 + lx;
    const int h  = h0 + ty;

    const float* tgtb = tgt + ((long long)b * CC + c0) * HW;
    const float* srcp = src + (((long long)b * CC + c0) * HH + h) * WW + w;

    // ---- staging: precompute 5 offsets/masks once, then unrolled LDG/STS ----
    int goff[5];
    bool val[5];
#pragma unroll
    for (int k = 0; k < 5; k++) {
        int pos = tid + k * NTHREADS;     // 0..639
        int r   = pos / HALO_W;
        int cl  = pos - r * HALO_W;
        int gr  = h0 - RR + r;
        int gc  = w0 - RR + cl;
        val[k]  = ((unsigned)gr < (unsigned)HH) & ((unsigned)gc < (unsigned)WW);
        goff[k] = gr * WW + gc;
    }
#pragma unroll
    for (int ch = 0; ch < CPK; ch++) {
        const float* tc = tgtb + ch * HW;
        float* sc = sm + ch * HALO_N;
#pragma unroll
        for (int k = 0; k < 5; k++)
            sc[tid + k * NTHREADS] = val[k] ? tc[goff[k]] : 0.f;
    }
    __syncthreads();

    // ---- compute: 17 packed accumulators over CPK channels ----
    uint64_t acc[SS];
#pragma unroll
    for (int s = 0; s < SS; s++) acc[s] = 0ull;

    const int rowbase = (ty + RR) * HALO_W + lx;     // this thread's row, col lx

    // 1-deep software pipeline on the src pixel-pair load
    uint64_t sv_cur = *(const uint64_t*)(srcp);

#pragma unroll
    for (int ch = 0; ch < CPK; ch++) {
        uint64_t sv_nxt = 0ull;
        if (ch + 1 < CPK)
            sv_nxt = *(const uint64_t*)(srcp + (ch + 1) * HW);

        const float* smc = sm + ch * HALO_N;
        // horizontal row: 10 values = cols lx..lx+9 (5 aligned LDS.64)
        float2 t0 = *(const float2*)(smc + rowbase + 0);
        float2 t1 = *(const float2*)(smc + rowbase + 2);
        float2 t2 = *(const float2*)(smc + rowbase + 4);
        float2 t3 = *(const float2*)(smc + rowbase + 6);
        float2 t4 = *(const float2*)(smc + rowbase + 8);

        // s=0: center pair (v4,v5)
        ffma2(acc[0], sv_cur, pack2(t2.x, t2.y));
        // i=1: L=(v3,v4) R=(v5,v6)
        ffma2(acc[3], sv_cur, pack2(t1.y, t2.x));
        ffma2(acc[4], sv_cur, pack2(t2.y, t3.x));
        // i=2: L=(v2,v3)  R=(v6,v7)
        ffma2(acc[7], sv_cur, pack2(t1.x, t1.y));
        ffma2(acc[8], sv_cur, pack2(t3.x, t3.y));
        // i=3: L=(v1,v2) R=(v7,v8)
        ffma2(acc[11], sv_cur, pack2(t0.y, t1.x));
        ffma2(acc[12], sv_cur, pack2(t3.y, t4.x));
        // i=4: L=(v0,v1)  R=(v8,v9)
        ffma2(acc[15], sv_cur, pack2(t0.x, t0.y));
        ffma2(acc[16], sv_cur, pack2(t4.x, t4.y));

        // vertical: s=4i-3 (up), s=4i-2 (down): aligned pairs at col lx+RR
#pragma unroll
        for (int i2 = 1; i2 <= RR; i2++) {
            uint64_t tu = *(const uint64_t*)(smc + (ty + RR - i2) * HALO_W + lx + RR);
            uint64_t td = *(const uint64_t*)(smc + (ty + RR + i2) * HALO_W + lx + RR);
            ffma2(acc[4 * i2 - 3], sv_cur, tu);
            ffma2(acc[4 * i2 - 2], sv_cur, td);
        }

        sv_cur = sv_nxt;
    }

    // ---- combine partials across chunks via float2 atomics ----
    float* ob = out + ((((long long)b * SS) * HH) + h) * WW + w;
#pragma unroll
    for (int s = 0; s < SS; s++) {
        float2 o;
        asm("mov.b64 {%0, %1}, %2;" : "=f"(o.x), "=f"(o.y) : "l"(acc[s]));
        atomicAdd((float2*)(ob + s * HW), o);
    }
}

extern "C" void kernel_launch(void* const* d_in, const int* in_sizes, int n_in,
                              void* d_out, int out_size) {
    const float* src = (const float*)d_in[0];
    const float* tgt = (const float*)d_in[1];
    float* out = (float*)d_out;

    cudaMemsetAsync(out, 0, (size_t)out_size * sizeof(float), 0);

    dim3 block(BX, BY);
    dim3 grid(WW / TW, HH / TH, BB * NCHUNK);   // 5 x 12 x 64 = 3840 CTAs
    cost_volume_kernel<<<grid, block>>>(src, tgt, out);
}

// round 7
// speedup vs baseline: 1.0696x; 1.0609x over previous
#include <cuda_runtime.h>
#include <cstdint>

// Problem constants (fixed by setup_inputs)
#define BB 4
#define CC 128
#define HH 96
#define WW 160
#define RR 4
#define SS 17   // 1 + 4*R

// Tiling
#define TW 32
#define TH 8
#define BX 16          // threads in w (2 px each)
#define BY 8
#define NTHREADS (BX * BY)   // 128
#define HALO_W (TW + 2 * RR) // 40
#define HALO_H (TH + 2 * RR) // 16
#define HALO_N (HALO_H * HALO_W)  // 640 floats
#define HALO_P (HALO_N / 2)       // 320 float2 pairs
#define HALO_PW (HALO_W / 2)      // 20 pairs per row

#define NCHUNK 16
#define CPK (CC / NCHUNK)    // 8 channels per chunk
#define HW (HH * WW)

// packed f32x2 fma: acc = a*b + acc  (elementwise on 2 floats)
__device__ __forceinline__ void ffma2(uint64_t& acc, uint64_t a, uint64_t b) {
    asm("fma.rn.f32x2 %0, %1, %2, %0;" : "+l"(acc) : "l"(a), "l"(b));
}
__device__ __forceinline__ uint64_t pack2(float lo, float hi) {
    uint64_t r;
    asm("mov.b64 %0, {%1, %2};" : "=l"(r) : "f"(lo), "f"(hi));
    return r;
}
// cp.async 8B with zero-fill when sz==0
__device__ __forceinline__ void cp_async8(uint32_t saddr, const void* gaddr, int sz) {
    asm volatile("cp.async.ca.shared.global [%0], [%1], 8, %2;"
                 :: "r"(saddr), "l"(gaddr), "r"(sz) : "memory");
}

__global__ __launch_bounds__(NTHREADS, 8)
void cost_volume_kernel(const float* __restrict__ src,
                        const float* __restrict__ tgt,
                        float* __restrict__ out) {
    __shared__ float sm[CPK * HALO_N];   // 8 * 640 * 4B = 20 KB

    const int tx = threadIdx.x;
    const int ty = threadIdx.y;
    const int tid = ty * BX + tx;
    const int w0 = blockIdx.x * TW;
    const int h0 = blockIdx.y * TH;
    const int b     = blockIdx.z >> 4;   // NCHUNK = 16
    const int chunk = blockIdx.z & 15;
    const int c0 = chunk * CPK;
    const int lx = 2 * tx;
    const int w  = w0 + lx;
    const int h  = h0 + ty;

    const float* tgtb = tgt + ((long long)b * CC + c0) * HW;
    const float* srcp = src + (((long long)b * CC + c0) * HH + h) * WW + w;

    // ---- staging: float2 pairs via cp.async with border zero-fill ----
    // 320 pairs / 128 threads -> 3 slots (slot 2 active for tid < 64)
    int goff[3], sz[3];
#pragma unroll
    for (int k = 0; k < 3; k++) {
        int pos2 = tid + k * NTHREADS;      // pair index 0..319 (or 320+ for k=2)
        int r    = pos2 / HALO_PW;
        int c2   = pos2 - r * HALO_PW;
        int gr   = h0 - RR + r;
        int gc   = w0 - RR + 2 * c2;        // even; pair fully in or fully out
        bool ok  = ((unsigned)gr < (unsigned)HH) & ((unsigned)gc < (unsigned)WW);
        goff[k] = gr * WW + gc;
        sz[k]   = ok ? 8 : 0;
    }
    const uint32_t sbase = (uint32_t)__cvta_generic_to_shared(sm);
#pragma unroll
    for (int ch = 0; ch < CPK; ch++) {
        const float* tc = tgtb + ch * HW;
        const uint32_t sc = sbase + ch * (HALO_N * 4);
#pragma unroll
        for (int k = 0; k < 3; k++) {
            if (k < 2 || tid < HALO_P - 2 * NTHREADS)
                cp_async8(sc + (tid + k * NTHREADS) * 8, tc + goff[k], sz[k]);
        }
    }
    asm volatile("cp.async.commit_group;" ::: "memory");
    asm volatile("cp.async.wait_group 0;" ::: "memory");
    __syncthreads();

    // ---- compute: 17 packed accumulators over CPK channels ----
    uint64_t acc[SS];
#pragma unroll
    for (int s = 0; s < SS; s++) acc[s] = 0ull;

    const int rowbase = (ty + RR) * HALO_W + lx;     // this thread's row, col lx

    // 1-deep software pipeline on the src pixel-pair load
    uint64_t sv_cur = *(const uint64_t*)(srcp);

#pragma unroll
    for (int ch = 0; ch < CPK; ch++) {
        uint64_t sv_nxt = 0ull;
        if (ch + 1 < CPK)
            sv_nxt = *(const uint64_t*)(srcp + (ch + 1) * HW);

        const float* smc = sm + ch * HALO_N;
        // horizontal row: 10 values = cols lx..lx+9 (5 aligned LDS.64)
        float2 t0 = *(const float2*)(smc + rowbase + 0);
        float2 t1 = *(const float2*)(smc + rowbase + 2);
        float2 t2 = *(const float2*)(smc + rowbase + 4);
        float2 t3 = *(const float2*)(smc + rowbase + 6);
        float2 t4 = *(const float2*)(smc + rowbase + 8);

        // s=0: center pair (v4,v5)
        ffma2(acc[0], sv_cur, pack2(t2.x, t2.y));
        // i=1: L=(v3,v4) R=(v5,v6)
        ffma2(acc[3], sv_cur, pack2(t1.y, t2.x));
        ffma2(acc[4], sv_cur, pack2(t2.y, t3.x));
        // i=2: L=(v2,v3)  R=(v6,v7)
        ffma2(acc[7], sv_cur, pack2(t1.x, t1.y));
        ffma2(acc[8], sv_cur, pack2(t3.x, t3.y));
        // i=3: L=(v1,v2) R=(v7,v8)
        ffma2(acc[11], sv_cur, pack2(t0.y, t1.x));
        ffma2(acc[12], sv_cur, pack2(t3.y, t4.x));
        // i=4: L=(v0,v1)  R=(v8,v9)
        ffma2(acc[15], sv_cur, pack2(t0.x, t0.y));
        ffma2(acc[16], sv_cur, pack2(t4.x, t4.y));

        // vertical: s=4i-3 (up), s=4i-2 (down): aligned pairs at col lx+RR
#pragma unroll
        for (int i2 = 1; i2 <= RR; i2++) {
            uint64_t tu = *(const uint64_t*)(smc + (ty + RR - i2) * HALO_W + lx + RR);
            uint64_t td = *(const uint64_t*)(smc + (ty + RR + i2) * HALO_W + lx + RR);
            ffma2(acc[4 * i2 - 3], sv_cur, tu);
            ffma2(acc[4 * i2 - 2], sv_cur, td);
        }

        sv_cur = sv_nxt;
    }

    // ---- combine partials across chunks via float2 atomics (RED) ----
    float* ob = out + ((((long long)b * SS) * HH) + h) * WW + w;
#pragma unroll
    for (int s = 0; s < SS; s++) {
        float2 o;
        asm("mov.b64 {%0, %1}, %2;" : "=f"(o.x), "=f"(o.y) : "l"(acc[s]));
        atomicAdd((float2*)(ob + s * HW), o);
    }
}

extern "C" void kernel_launch(void* const* d_in, const int* in_sizes, int n_in,
                              void* d_out, int out_size) {
    const float* src = (const float*)d_in[0];
    const float* tgt = (const float*)d_in[1];
    float* out = (float*)d_out;

    cudaMemsetAsync(out, 0, (size_t)out_size * sizeof(float), 0);

    dim3 block(BX, BY);
    dim3 grid(WW / TW, HH / TH, BB * NCHUNK);   // 5 x 12 x 64 = 3840 CTAs
    cost_volume_kernel<<<grid, block>>>(src, tgt, out);
}

// round 8
// speedup vs baseline: 1.0708x; 1.0011x over previous
#include <cuda_runtime.h>
#include <cstdint>

// Problem constants (fixed by setup_inputs)
#define BB 4
#define CC 128
#define HH 96
#define WW 160
#define RR 4
#define SS 17   // 1 + 4*R

// Tiling
#define TW 32
#define TH 8
#define BX 16          // threads in w (2 px each)
#define BY 8
#define NTHREADS (BX * BY)   // 128
#define HALO_W (TW + 2 * RR) // 40
#define HALO_H (TH + 2 * RR) // 16
#define HALO_N (HALO_H * HALO_W)  // 640 floats per channel
#define HALO_P (HALO_N / 2)       // 320 float2 pairs
#define HALO_PW (HALO_W / 2)      // 20 pairs per row

#define NCHUNK 8
#define CPK (CC / NCHUNK)    // 16 channels per chunk
#define STAGE_CH 4           // channels per pipeline stage
#define NSTAGE (CPK / STAGE_CH)  // 4 stages
#define HW (HH * WW)

// packed f32x2 fma: acc = a*b + acc
__device__ __forceinline__ void ffma2(uint64_t& acc, uint64_t a, uint64_t b) {
    asm("fma.rn.f32x2 %0, %1, %2, %0;" : "+l"(acc) : "l"(a), "l"(b));
}
__device__ __forceinline__ uint64_t pack2(float lo, float hi) {
    uint64_t r;
    asm("mov.b64 %0, {%1, %2};" : "=l"(r) : "f"(lo), "f"(hi));
    return r;
}
__device__ __forceinline__ void cp_async8(uint32_t saddr, const void* gaddr, int sz) {
    asm volatile("cp.async.ca.shared.global [%0], [%1], 8, %2;"
                 :: "r"(saddr), "l"(gaddr), "r"(sz) : "memory");
}

__global__ __launch_bounds__(NTHREADS, 8)
void cost_volume_kernel(const float* __restrict__ src,
                        const float* __restrict__ tgt,
                        float* __restrict__ out) {
    // two staging buffers of STAGE_CH channels each: 2 * 4 * 640 * 4B = 20 KB
    __shared__ float sm[2][STAGE_CH * HALO_N];

    const int tx = threadIdx.x;
    const int ty = threadIdx.y;
    const int tid = ty * BX + tx;
    const int w0 = blockIdx.x * TW;
    const int h0 = blockIdx.y * TH;
    const int b     = blockIdx.z >> 3;   // NCHUNK = 8
    const int chunk = blockIdx.z & 7;
    const int c0 = chunk * CPK;
    const int lx = 2 * tx;
    const int w  = w0 + lx;
    const int h  = h0 + ty;

    const float* tgtb = tgt + ((long long)b * CC + c0) * HW;
    const float* srcp = src + (((long long)b * CC + c0) * HH + h) * WW + w;

    // staging offsets (channel-invariant): 320 pairs / 128 threads -> 3 slots
    int goff[3], szv[3];
#pragma unroll
    for (int k = 0; k < 3; k++) {
        int pos2 = tid + k * NTHREADS;      // pair index
        int r    = pos2 / HALO_PW;
        int c2   = pos2 - r * HALO_PW;
        int gr   = h0 - RR + r;
        int gc   = w0 - RR + 2 * c2;        // pair fully in or fully out
        bool ok  = ((unsigned)gr < (unsigned)HH) & ((unsigned)gc < (unsigned)WW);
        goff[k] = gr * WW + gc;
        szv[k]  = ok ? 8 : 0;
    }
    const uint32_t sbase = (uint32_t)__cvta_generic_to_shared(&sm[0][0]);
    const bool k2on = tid < HALO_P - 2 * NTHREADS;   // slot 2 active for tid<64

    // stage loader: stage st -> buffer st&1, channels [st*4, st*4+4)
    auto stage_load = [&](int st) {
        const uint32_t sb = sbase + (st & 1) * (STAGE_CH * HALO_N * 4);
        const float* tb = tgtb + st * STAGE_CH * HW;
#pragma unroll
        for (int ch = 0; ch < STAGE_CH; ch++) {
            const float* tc = tb + ch * HW;
            const uint32_t sc = sb + ch * (HALO_N * 4);
            cp_async8(sc + tid * 8,                  tc + goff[0], szv[0]);
            cp_async8(sc + (tid + NTHREADS) * 8,     tc + goff[1], szv[1]);
            if (k2on)
                cp_async8(sc + (tid + 2 * NTHREADS) * 8, tc + goff[2], szv[2]);
        }
        asm volatile("cp.async.commit_group;" ::: "memory");
    };

    stage_load(0);

    uint64_t acc[SS];
#pragma unroll
    for (int s = 0; s < SS; s++) acc[s] = 0ull;

    const int rowbase = (ty + RR) * HALO_W + lx;
    uint64_t sv_cur = *(const uint64_t*)(srcp);   // channel 0 src pair

#pragma unroll
    for (int st = 0; st < NSTAGE; st++) {
        if (st + 1 < NSTAGE) {
            stage_load(st + 1);
            asm volatile("cp.async.wait_group 1;" ::: "memory");
        } else {
            asm volatile("cp.async.wait_group 0;" ::: "memory");
        }
        __syncthreads();

        const float* smb = &sm[st & 1][0];
#pragma unroll
        for (int ch = 0; ch < STAGE_CH; ch++) {
            const int gch = st * STAGE_CH + ch;
            uint64_t sv_nxt = 0ull;
            if (gch + 1 < CPK)
                sv_nxt = *(const uint64_t*)(srcp + (gch + 1) * HW);

            const float* smc = smb + ch * HALO_N;
            float2 t0 = *(const float2*)(smc + rowbase + 0);
            float2 t1 = *(const float2*)(smc + rowbase + 2);
            float2 t2 = *(const float2*)(smc + rowbase + 4);
            float2 t3 = *(const float2*)(smc + rowbase + 6);
            float2 t4 = *(const float2*)(smc + rowbase + 8);

            ffma2(acc[0],  sv_cur, pack2(t2.x, t2.y));
            ffma2(acc[3],  sv_cur, pack2(t1.y, t2.x));
            ffma2(acc[4],  sv_cur, pack2(t2.y, t3.x));
            ffma2(acc[7],  sv_cur, pack2(t1.x, t1.y));
            ffma2(acc[8],  sv_cur, pack2(t3.x, t3.y));
            ffma2(acc[11], sv_cur, pack2(t0.y, t1.x));
            ffma2(acc[12], sv_cur, pack2(t3.y, t4.x));
            ffma2(acc[15], sv_cur, pack2(t0.x, t0.y));
            ffma2(acc[16], sv_cur, pack2(t4.x, t4.y));

#pragma unroll
            for (int i2 = 1; i2 <= RR; i2++) {
                uint64_t tu = *(const uint64_t*)(smc + (ty + RR - i2) * HALO_W + lx + RR);
                uint64_t td = *(const uint64_t*)(smc + (ty + RR + i2) * HALO_W + lx + RR);
                ffma2(acc[4 * i2 - 3], sv_cur, tu);
                ffma2(acc[4 * i2 - 2], sv_cur, td);
            }
            sv_cur = sv_nxt;
        }
        __syncthreads();   // buffer reuse fence before next stage_load overwrite
    }

    // combine partials across chunks via float2 atomics
    float* ob = out + ((((long long)b * SS) * HH) + h) * WW + w;
#pragma unroll
    for (int s = 0; s < SS; s++) {
        float2 o;
        asm("mov.b64 {%0, %1}, %2;" : "=f"(o.x), "=f"(o.y) : "l"(acc[s]));
        atomicAdd((float2*)(ob + s * HW), o);
    }
}

extern "C" void kernel_launch(void* const* d_in, const int* in_sizes, int n_in,
                              void* d_out, int out_size) {
    const float* src = (const float*)d_in[0];
    const float* tgt = (const float*)d_in[1];
    float* out = (float*)d_out;

    cudaMemsetAsync(out, 0, (size_t)out_size * sizeof(float), 0);

    dim3 block(BX, BY);
    dim3 grid(WW / TW, HH / TH, BB * NCHUNK);   // 5 x 12 x 32 = 1920 CTAs
    cost_volume_kernel<<<grid, block>>>(src, tgt, out);
}